// round 12
// baseline (speedup 1.0000x reference)
#include <cuda_runtime.h>
#include <cuda_fp16.h>

#define DD   256
#define BB   4
#define LXN  512
#define LMN  512

#define TXK  32
#define TMK  64
#define S1LD 34      // fp32 leading dim; rows 8B-aligned -> float2 access
#define S2LD 68      // fp32 leading dim; rows 16B-aligned -> float4 access

#define GK2  128     // half2 k-index count (K=256)
#define GLD  68      // gemm smem leading dim (rows + pad), half2 units

__device__ float g_item1t[BB * DD * LXN];   // [b][d][x] fp32
__device__ float g_item2c[BB * DD * LMN];   // [b][d][compacted m] fp32
__device__ int   g_midx[BB * LMN];          // compacted -> original m
__device__ int   g_pos [BB * LMN];          // original m -> compacted (-1)
__device__ int   g_cnt [BB];
__device__ int   g_prep_flag;               // release/acquire: #batches compacted

__device__ __forceinline__ float fast_tanh(float x) {
    float y;
    asm("tanh.approx.f32 %0, %1;" : "=f"(y) : "f"(x));
    return y;
}

// clamp +-2.5 poly: x*(a + b*x^2 + c*x^4); max abs err ~0.08, exact at clamp
__device__ __forceinline__ float ptanh(float x) {
    float xc = fminf(fmaxf(x, -2.5f), 2.5f);
    float t  = xc * xc;
    return xc * fmaf(t, fmaf(t, 0.018033f, -0.20549f), 0.97444f);
}

extern __shared__ __align__(16) char dynsm[];

// ---------------------------------------------------------------------------
// Fused: mask compaction (4 designated CTAs) + output prefill + NT-GEMM pair.
// which==0: x*W1^T + b1 -> g_item1t (transposed [b][d][x] fp32)
// which==1: mem*W2^T    -> g_item2c (scatter via g_pos; waits on prep flag)
// ---------------------------------------------------------------------------
__global__ __launch_bounds__(256) void gemm_h(const int* __restrict__ mask,
                                              const float* __restrict__ Xin,
                                              const float* __restrict__ Min,
                                              const float* __restrict__ W1,
                                              const float* __restrict__ W2,
                                              const float* __restrict__ b1,
                                              float4* __restrict__ out4,
                                              int n4) {
    __half2* As2 = (__half2*)dynsm;             // [GK2][GLD]
    __half2* Ws2 = As2 + GK2 * GLD;             // [GK2][GLD]

    const int tid = threadIdx.x;
    const int which = blockIdx.z;

    // --- prep: 4 designated CTAs compact the mask for their batch
    if (which == 0 && blockIdx.y == 0 && blockIdx.x < BB) {
        const int b = blockIdx.x;
        const int lane = tid & 31, w = tid >> 5;
        __shared__ int wcnt[8], woff[8], s_tot;
        int base = 0;
        #pragma unroll
        for (int r = 0; r < 2; ++r) {
            const int mp = tid + r * 256;
            int flag = mask[b * LMN + mp] != 0;
            unsigned bal = __ballot_sync(0xffffffffu, flag);
            int pre = __popc(bal & ((1u << lane) - 1u));
            if (lane == 0) wcnt[w] = __popc(bal);
            __syncthreads();
            if (tid == 0) {
                int s = 0;
                for (int i = 0; i < 8; ++i) { woff[i] = s; s += wcnt[i]; }
                s_tot = s;
            }
            __syncthreads();
            int p = base + woff[w] + pre;
            g_pos[b * LMN + mp] = flag ? p : -1;
            if (flag) g_midx[b * LMN + p] = mp;
            base += s_tot;
            __syncthreads();
        }
        if (tid == 0) g_cnt[b] = base;
        const int n = base;   // pad indices for the tail tile's int4 reads
        if (n > 0) {
            const int padded = (n + TMK - 1) / TMK * TMK;
            for (int q = tid; q < padded; q += 256)
                if (q >= n) g_midx[b * LMN + q] = g_midx[b * LMN + n - 1];
        }
        __syncthreads();
        if (tid == 0) { __threadfence(); atomicAdd(&g_prep_flag, 1); }
    }

    // --- output prefill slice (256 CTAs x 256 thr cover n4 = 1M float4)
    {
        const int bid = blockIdx.x + 32 * (blockIdx.y + 4 * blockIdx.z);
        const float4 v = make_float4(-10000.f, -10000.f, -10000.f, -10000.f);
        for (int i = bid * 256 + tid; i < n4; i += 256 * 256)
            out4[i] = v;
    }

    const float* A = which ? Min : Xin;
    const float* W = which ? W2  : W1;

    const int m0 = blockIdx.x * 64;
    const int n0 = blockIdx.y * 64;
    const int tx = tid & 15;
    const int ty = tid >> 4;
    const int lr = tid >> 2;        // load row 0..63
    const int lj = tid & 3;         // float4 column group

    // --- single load phase: full 64x256 panels for A and W, deep MLP
    #pragma unroll
    for (int i = 0; i < 16; ++i) {
        const int j4 = lj + (i << 2);                 // float4 idx 0..63
        float4 av = *(const float4*)&A[(m0 + lr) * DD + j4 * 4];
        float4 wv = *(const float4*)&W[(n0 + lr) * DD + j4 * 4];
        const int k2 = 2 * j4;
        As2[(k2 + 0) * GLD + lr] = __floats2half2_rn(av.x, av.y);
        As2[(k2 + 1) * GLD + lr] = __floats2half2_rn(av.z, av.w);
        Ws2[(k2 + 0) * GLD + lr] = __floats2half2_rn(wv.x, wv.y);
        Ws2[(k2 + 1) * GLD + lr] = __floats2half2_rn(wv.z, wv.w);
    }
    __syncthreads();

    float accf[4][4] = {};
    const __half2 hz = __float2half2_rn(0.f);

    #pragma unroll 1
    for (int kc = 0; kc < GK2; kc += 32) {     // flush fp32 every 64 k
        __half2 acc2[4][4];
        #pragma unroll
        for (int i = 0; i < 4; ++i)
            #pragma unroll
            for (int j = 0; j < 4; ++j) acc2[i][j] = hz;

        #pragma unroll 8
        for (int k2 = kc; k2 < kc + 32; ++k2) {
            uint4 au = *(const uint4*)&As2[k2 * GLD + tx * 4];
            uint4 wu = *(const uint4*)&Ws2[k2 * GLD + ty * 4];
            __half2 ar[4], wr[4];
            ar[0] = *reinterpret_cast<__half2*>(&au.x);
            ar[1] = *reinterpret_cast<__half2*>(&au.y);
            ar[2] = *reinterpret_cast<__half2*>(&au.z);
            ar[3] = *reinterpret_cast<__half2*>(&au.w);
            wr[0] = *reinterpret_cast<__half2*>(&wu.x);
            wr[1] = *reinterpret_cast<__half2*>(&wu.y);
            wr[2] = *reinterpret_cast<__half2*>(&wu.z);
            wr[3] = *reinterpret_cast<__half2*>(&wu.w);
            #pragma unroll
            for (int i = 0; i < 4; ++i)
                #pragma unroll
                for (int j = 0; j < 4; ++j)
                    acc2[i][j] = __hfma2(ar[i], wr[j], acc2[i][j]);
        }
        #pragma unroll
        for (int i = 0; i < 4; ++i)
            #pragma unroll
            for (int j = 0; j < 4; ++j) {
                float2 t = __half22float2(acc2[i][j]);
                accf[i][j] += t.x + t.y;
            }
    }

    const int r_base = m0 + tx * 4;
    const int bb = r_base >> 9;
    const int lb = r_base & 511;

    if (!which) {
        float4 bv = *(const float4*)&b1[n0 + ty * 4];
        float bj[4] = {bv.x, bv.y, bv.z, bv.w};
        #pragma unroll
        for (int j = 0; j < 4; ++j) {
            int d = n0 + ty * 4 + j;
            float4 v;
            v.x = accf[0][j] + bj[j];
            v.y = accf[1][j] + bj[j];
            v.z = accf[2][j] + bj[j];
            v.w = accf[3][j] + bj[j];
            *(float4*)&g_item1t[((bb * DD + d) * LXN) + lb] = v;
        }
    } else {
        // acquire: wait until all 4 batches are compacted (set long ago by now)
        if (tid == 0) {
            while (atomicAdd(&g_prep_flag, 0) < BB) { }
            __threadfence();
        }
        __syncthreads();

        int4 pi = *(const int4*)&g_pos[bb * LMN + lb];
        int pos[4] = {pi.x, pi.y, pi.z, pi.w};
        #pragma unroll
        for (int j = 0; j < 4; ++j) {
            int d = n0 + ty * 4 + j;
            float* dst = g_item2c + (bb * DD + d) * LMN;
            #pragma unroll
            for (int i = 0; i < 4; ++i)
                if (pos[i] >= 0)
                    dst[pos[i]] = accf[i][j];
        }
    }
}

// ---------------------------------------------------------------------------
// attn over ACTIVE m-columns, fp32. Hybrid tanh: d%4==3 -> fp32 polynomial
// (FMA pipe), else MUFU tanh.approx.f32. Tail stores predicated on n_act.
// Also resets g_prep_flag for the next graph replay (runs after gemm_h).
// ---------------------------------------------------------------------------
__global__ __launch_bounds__(256) void attn_kernel(const float* __restrict__ Wt,
                                                   float* __restrict__ out) {
    // reset the prep flag for the next replay (before any early return)
    if (blockIdx.x == 0 && blockIdx.y == 0 && blockIdx.z == 0 &&
        threadIdx.x == 0)
        g_prep_flag = 0;

    const int b  = blockIdx.z;
    const int m0 = blockIdx.y * TMK;
    const int n_act = g_cnt[b];
    if (m0 >= n_act) return;

    float* s1  = (float*)dynsm;          // [DD][S1LD]
    float* s2  = s1 + DD * S1LD;         // [DD][S2LD]
    float* swt = s2 + DD * S2LD;         // [DD]

    const int tid = threadIdx.x;
    const int x0 = blockIdx.x * TXK;

    {
        const int d = tid;
        // s1 row: 32 floats via float2 (row base 8B-aligned only)
        const float2* p1 = (const float2*)(g_item1t + (b * DD + d) * LXN + x0);
        float2* q1 = (float2*)(s1 + d * S1LD);
        #pragma unroll
        for (int j = 0; j < 16; ++j) q1[j] = p1[j];

        // s2 row: 64 floats via float4 (row base 16B-aligned)
        const float4* p2 = (const float4*)(g_item2c + (b * DD + d) * LMN + m0);
        float* q2 = s2 + d * S2LD;
        #pragma unroll
        for (int j = 0; j < 16; ++j) *(float4*)(q2 + j * 4) = p2[j];

        swt[d] = Wt[d];
    }
    __syncthreads();

    const int tx = tid & 15;
    const int tm = tid >> 4;
    const float* s1p = s1 + tx * 2;
    const float* s2p = s2 + tm * 4;

    float acc[2][4] = {};

    #pragma unroll 1
    for (int d0 = 0; d0 < DD; d0 += 4) {
        #pragma unroll
        for (int dd = 0; dd < 4; ++dd) {
            const int d = d0 + dd;
            float  w  = swt[d];
            float2 a  = *(const float2*)(s1p + d * S1LD);
            float4 m4 = *(const float4*)(s2p + d * S2LD);
            if (dd != 3) {   // MUFU path (3 of 4)
                acc[0][0] += fast_tanh(a.x + m4.x) * w;
                acc[0][1] += fast_tanh(a.x + m4.y) * w;
                acc[0][2] += fast_tanh(a.x + m4.z) * w;
                acc[0][3] += fast_tanh(a.x + m4.w) * w;
                acc[1][0] += fast_tanh(a.y + m4.x) * w;
                acc[1][1] += fast_tanh(a.y + m4.y) * w;
                acc[1][2] += fast_tanh(a.y + m4.z) * w;
                acc[1][3] += fast_tanh(a.y + m4.w) * w;
            } else {         // polynomial path (1 of 4) on the FMA/ALU pipes
                acc[0][0] += ptanh(a.x + m4.x) * w;
                acc[0][1] += ptanh(a.x + m4.y) * w;
                acc[0][2] += ptanh(a.x + m4.z) * w;
                acc[0][3] += ptanh(a.x + m4.w) * w;
                acc[1][0] += ptanh(a.y + m4.x) * w;
                acc[1][1] += ptanh(a.y + m4.y) * w;
                acc[1][2] += ptanh(a.y + m4.z) * w;
                acc[1][3] += ptanh(a.y + m4.w) * w;
            }
        }
    }

    // predicated scatter-store: only truly active columns write
    const int c0 = m0 + tm * 4;
    int4 mi = *(const int4*)&g_midx[b * LMN + c0];
    bool v0 = (c0 + 0) < n_act, v1 = (c0 + 1) < n_act;
    bool v2 = (c0 + 2) < n_act, v3 = (c0 + 3) < n_act;
    const int x = x0 + tx * 2;
    float* r0 = out + (b * LXN + x) * (long)LMN;
    float* r1 = r0 + LMN;
    if (v0) { r0[mi.x] = acc[0][0]; r1[mi.x] = acc[1][0]; }
    if (v1) { r0[mi.y] = acc[0][1]; r1[mi.y] = acc[1][1]; }
    if (v2) { r0[mi.z] = acc[0][2]; r1[mi.z] = acc[1][2]; }
    if (v3) { r0[mi.w] = acc[0][3]; r1[mi.w] = acc[1][3]; }
}

// ---------------------------------------------------------------------------

extern "C" void kernel_launch(void* const* d_in, const int* in_sizes, int n_in,
                              void* d_out, int out_size) {
    const float* x      = (const float*)d_in[0];
    const float* memory = (const float*)d_in[1];
    const int*   mask   = (const int*)d_in[2];
    const float* W1     = (const float*)d_in[3];
    const float* b1     = (const float*)d_in[4];
    const float* W2     = (const float*)d_in[5];
    const float* Wt     = (const float*)d_in[6];
    float* out = (float*)d_out;

    // 1) fused: compaction + prefill + projections (one launch)
    const int gsmem = 2 * GK2 * GLD * (int)sizeof(__half2);   // 69632 B
    cudaFuncSetAttribute(gemm_h,
                         cudaFuncAttributeMaxDynamicSharedMemorySize, gsmem);
    dim3 ggrid(2048 / 64, DD / 64, 2);
    gemm_h<<<ggrid, 256, gsmem>>>(mask, x, memory, W1, W2, b1,
                                  (float4*)out, out_size / 4);

    // 2) attention over active columns (fp32, 3:1 MUFU:poly hybrid)
    const int asmem = (DD * S1LD + DD * S2LD + DD) * 4;
    cudaFuncSetAttribute(attn_kernel,
                         cudaFuncAttributeMaxDynamicSharedMemorySize, asmem);
    dim3 agrid(LXN / TXK, LMN / TMK, BB);
    attn_kernel<<<agrid, 256, asmem>>>(Wt, out);
}

// round 13
// speedup vs baseline: 1.0009x; 1.0009x over previous
#include <cuda_runtime.h>
#include <cuda_fp16.h>

#define DD   256
#define BB   4
#define LXN  512
#define LMN  512

#define TXK  32
#define TMK  64
#define S1LD 34      // fp32 leading dim; rows 8B-aligned -> float2 access
#define S2LD 68      // fp32 leading dim; rows 16B-aligned -> float4 access

#define GK2  128     // half2 k-index count (K=256)
#define GLD  68      // gemm smem leading dim (rows + pad), half2 units

__device__ float g_item1t[BB * DD * LXN];   // [b][d][x] fp32
__device__ float g_item2c[BB * DD * LMN];   // [b][d][compacted m] fp32
__device__ int   g_midx[BB * LMN];          // compacted -> original m
__device__ int   g_pos [BB * LMN];          // original m -> compacted (-1)
__device__ int   g_cnt [BB];

__device__ __forceinline__ float fast_tanh(float x) {
    float y;
    asm("tanh.approx.f32 %0, %1;" : "=f"(y) : "f"(x));
    return y;
}

// clamp +-2.5 poly: x*(a + b*x^2 + c*x^4); max abs err ~0.08, exact at clamp
__device__ __forceinline__ float ptanh(float x) {
    float xc = fminf(fmaxf(x, -2.5f), 2.5f);
    float t  = xc * xc;
    return xc * fmaf(t, fmaf(t, 0.018033f, -0.20549f), 0.97444f);
}

extern __shared__ __align__(16) char dynsm[];

// ---------------------------------------------------------------------------
// prep: stable mask compaction only (4 tiny CTAs)  [R10 structure]
// ---------------------------------------------------------------------------
__global__ __launch_bounds__(512) void prep_kernel(const int* __restrict__ mask) {
    const int b = blockIdx.x;
    const int t = threadIdx.x;
    const int lane = t & 31, w = t >> 5;

    int flag = mask[b * LMN + t] != 0;
    unsigned bal = __ballot_sync(0xffffffffu, flag);
    int pre = __popc(bal & ((1u << lane) - 1u));

    __shared__ int wcnt[16], woff[16], s_n;
    if (lane == 0) wcnt[w] = __popc(bal);
    __syncthreads();
    if (t == 0) {
        int s = 0;
        for (int i = 0; i < 16; ++i) { woff[i] = s; s += wcnt[i]; }
        s_n = s;
        g_cnt[b] = s;
    }
    __syncthreads();
    int p = woff[w] + pre;
    g_pos[b * LMN + t] = flag ? p : -1;
    if (flag) g_midx[b * LMN + p] = t;
    __syncthreads();

    const int n = s_n;   // pad indices for the tail tile's int4 reads
    if (n > 0) {
        const int padded = (n + TMK - 1) / TMK * TMK;
        if (t >= n && t < padded)
            g_midx[b * LMN + t] = g_midx[b * LMN + n - 1];
    }
}

// ---------------------------------------------------------------------------
// Fused NT-GEMM pair (single-load smem, HFMA2 core, fp32 out) + output
// prefill with -10000 at the kernel head. [R10 structure]
// ---------------------------------------------------------------------------
__global__ __launch_bounds__(256) void gemm_h(const float* __restrict__ Xin,
                                              const float* __restrict__ Min,
                                              const float* __restrict__ W1,
                                              const float* __restrict__ W2,
                                              const float* __restrict__ b1,
                                              float4* __restrict__ out4,
                                              int n4) {
    __half2* As2 = (__half2*)dynsm;             // [GK2][GLD]
    __half2* Ws2 = As2 + GK2 * GLD;             // [GK2][GLD]

    const int tid = threadIdx.x;

    // --- output prefill slice (256 CTAs x 256 thr cover n4 = 1M float4)
    {
        const int bid = blockIdx.x + 32 * (blockIdx.y + 4 * blockIdx.z);
        const float4 v = make_float4(-10000.f, -10000.f, -10000.f, -10000.f);
        for (int i = bid * 256 + tid; i < n4; i += 256 * 256)
            out4[i] = v;
    }

    const int which = blockIdx.z;
    const float* A = which ? Min : Xin;
    const float* W = which ? W2  : W1;

    const int m0 = blockIdx.x * 64;
    const int n0 = blockIdx.y * 64;
    const int tx = tid & 15;
    const int ty = tid >> 4;
    const int lr = tid >> 2;        // load row 0..63
    const int lj = tid & 3;         // float4 column group

    #pragma unroll
    for (int i = 0; i < 16; ++i) {
        const int j4 = lj + (i << 2);                 // float4 idx 0..63
        float4 av = *(const float4*)&A[(m0 + lr) * DD + j4 * 4];
        float4 wv = *(const float4*)&W[(n0 + lr) * DD + j4 * 4];
        const int k2 = 2 * j4;
        As2[(k2 + 0) * GLD + lr] = __floats2half2_rn(av.x, av.y);
        As2[(k2 + 1) * GLD + lr] = __floats2half2_rn(av.z, av.w);
        Ws2[(k2 + 0) * GLD + lr] = __floats2half2_rn(wv.x, wv.y);
        Ws2[(k2 + 1) * GLD + lr] = __floats2half2_rn(wv.z, wv.w);
    }
    __syncthreads();

    float accf[4][4] = {};
    const __half2 hz = __float2half2_rn(0.f);

    #pragma unroll 1
    for (int kc = 0; kc < GK2; kc += 32) {     // flush fp32 every 64 k
        __half2 acc2[4][4];
        #pragma unroll
        for (int i = 0; i < 4; ++i)
            #pragma unroll
            for (int j = 0; j < 4; ++j) acc2[i][j] = hz;

        #pragma unroll 8
        for (int k2 = kc; k2 < kc + 32; ++k2) {
            uint4 au = *(const uint4*)&As2[k2 * GLD + tx * 4];
            uint4 wu = *(const uint4*)&Ws2[k2 * GLD + ty * 4];
            __half2 ar[4], wr[4];
            ar[0] = *reinterpret_cast<__half2*>(&au.x);
            ar[1] = *reinterpret_cast<__half2*>(&au.y);
            ar[2] = *reinterpret_cast<__half2*>(&au.z);
            ar[3] = *reinterpret_cast<__half2*>(&au.w);
            wr[0] = *reinterpret_cast<__half2*>(&wu.x);
            wr[1] = *reinterpret_cast<__half2*>(&wu.y);
            wr[2] = *reinterpret_cast<__half2*>(&wu.z);
            wr[3] = *reinterpret_cast<__half2*>(&wu.w);
            #pragma unroll
            for (int i = 0; i < 4; ++i)
                #pragma unroll
                for (int j = 0; j < 4; ++j)
                    acc2[i][j] = __hfma2(ar[i], wr[j], acc2[i][j]);
        }
        #pragma unroll
        for (int i = 0; i < 4; ++i)
            #pragma unroll
            for (int j = 0; j < 4; ++j) {
                float2 t = __half22float2(acc2[i][j]);
                accf[i][j] += t.x + t.y;
            }
    }

    const int r_base = m0 + tx * 4;
    const int bb = r_base >> 9;
    const int lb = r_base & 511;

    if (!which) {
        float4 bv = *(const float4*)&b1[n0 + ty * 4];
        float bj[4] = {bv.x, bv.y, bv.z, bv.w};
        #pragma unroll
        for (int j = 0; j < 4; ++j) {
            int d = n0 + ty * 4 + j;
            float4 v;
            v.x = accf[0][j] + bj[j];
            v.y = accf[1][j] + bj[j];
            v.z = accf[2][j] + bj[j];
            v.w = accf[3][j] + bj[j];
            *(float4*)&g_item1t[((bb * DD + d) * LXN) + lb] = v;
        }
    } else {
        int4 pi = *(const int4*)&g_pos[bb * LMN + lb];
        int pos[4] = {pi.x, pi.y, pi.z, pi.w};
        #pragma unroll
        for (int j = 0; j < 4; ++j) {
            int d = n0 + ty * 4 + j;
            float* dst = g_item2c + (bb * DD + d) * LMN;
            #pragma unroll
            for (int i = 0; i < 4; ++i)
                if (pos[i] >= 0)
                    dst[pos[i]] = accf[i][j];
        }
    }
}

// ---------------------------------------------------------------------------
// attn over ACTIVE m-columns, fp32, 3:1 MUFU:poly hybrid (poly at d%4==3).
// NEW: 8-d unrolled groups with batched up-front loads -> deep LDS MLP and
// 64 independent tanh chains per group for the MUFU/FMA pipes.
// ---------------------------------------------------------------------------
__global__ __launch_bounds__(256) void attn_kernel(const float* __restrict__ Wt,
                                                   float* __restrict__ out) {
    const int b  = blockIdx.z;
    const int m0 = blockIdx.y * TMK;
    const int n_act = g_cnt[b];
    if (m0 >= n_act) return;

    float* s1  = (float*)dynsm;          // [DD][S1LD]
    float* s2  = s1 + DD * S1LD;         // [DD][S2LD]
    float* swt = s2 + DD * S2LD;         // [DD] (16B-aligned base)

    const int tid = threadIdx.x;
    const int x0 = blockIdx.x * TXK;

    {
        const int d = tid;
        const float2* p1 = (const float2*)(g_item1t + (b * DD + d) * LXN + x0);
        float2* q1 = (float2*)(s1 + d * S1LD);
        #pragma unroll
        for (int j = 0; j < 16; ++j) q1[j] = p1[j];

        const float4* p2 = (const float4*)(g_item2c + (b * DD + d) * LMN + m0);
        float* q2 = s2 + d * S2LD;
        #pragma unroll
        for (int j = 0; j < 16; ++j) *(float4*)(q2 + j * 4) = p2[j];

        swt[d] = Wt[d];
    }
    __syncthreads();

    const int tx = tid & 15;
    const int tm = tid >> 4;
    const float* s1p = s1 + tx * 2;
    const float* s2p = s2 + tm * 4;

    float acc[2][4] = {};

    #pragma unroll 1
    for (int d0 = 0; d0 < DD; d0 += 8) {
        // ---- batched load block: 18 independent LDS, one latency exposure
        float2 a[8];
        float4 m[8];
        float4 wA = *(const float4*)&swt[d0];
        float4 wB = *(const float4*)&swt[d0 + 4];
        #pragma unroll
        for (int dd = 0; dd < 8; ++dd) {
            a[dd] = *(const float2*)(s1p + (d0 + dd) * S1LD);
            m[dd] = *(const float4*)(s2p + (d0 + dd) * S2LD);
        }
        const float w[8] = {wA.x, wA.y, wA.z, wA.w, wB.x, wB.y, wB.z, wB.w};

        // ---- compute block: 64 independent tanh chains (48 MUFU, 16 poly)
        #pragma unroll
        for (int dd = 0; dd < 8; ++dd) {
            const float ww = w[dd];
            const float2 aa = a[dd];
            const float4 mm = m[dd];
            if ((dd & 3) != 3) {   // MUFU path (3 of 4)
                acc[0][0] += fast_tanh(aa.x + mm.x) * ww;
                acc[0][1] += fast_tanh(aa.x + mm.y) * ww;
                acc[0][2] += fast_tanh(aa.x + mm.z) * ww;
                acc[0][3] += fast_tanh(aa.x + mm.w) * ww;
                acc[1][0] += fast_tanh(aa.y + mm.x) * ww;
                acc[1][1] += fast_tanh(aa.y + mm.y) * ww;
                acc[1][2] += fast_tanh(aa.y + mm.z) * ww;
                acc[1][3] += fast_tanh(aa.y + mm.w) * ww;
            } else {               // polynomial path (1 of 4), FMA/ALU pipes
                acc[0][0] += ptanh(aa.x + mm.x) * ww;
                acc[0][1] += ptanh(aa.x + mm.y) * ww;
                acc[0][2] += ptanh(aa.x + mm.z) * ww;
                acc[0][3] += ptanh(aa.x + mm.w) * ww;
                acc[1][0] += ptanh(aa.y + mm.x) * ww;
                acc[1][1] += ptanh(aa.y + mm.y) * ww;
                acc[1][2] += ptanh(aa.y + mm.z) * ww;
                acc[1][3] += ptanh(aa.y + mm.w) * ww;
            }
        }
    }

    // predicated scatter-store: only truly active columns write
    const int c0 = m0 + tm * 4;
    int4 mi = *(const int4*)&g_midx[b * LMN + c0];
    bool v0 = (c0 + 0) < n_act, v1 = (c0 + 1) < n_act;
    bool v2 = (c0 + 2) < n_act, v3 = (c0 + 3) < n_act;
    const int x = x0 + tx * 2;
    float* r0 = out + (b * LXN + x) * (long)LMN;
    float* r1 = r0 + LMN;
    if (v0) { r0[mi.x] = acc[0][0]; r1[mi.x] = acc[1][0]; }
    if (v1) { r0[mi.y] = acc[0][1]; r1[mi.y] = acc[1][1]; }
    if (v2) { r0[mi.z] = acc[0][2]; r1[mi.z] = acc[1][2]; }
    if (v3) { r0[mi.w] = acc[0][3]; r1[mi.w] = acc[1][3]; }
}

// ---------------------------------------------------------------------------

extern "C" void kernel_launch(void* const* d_in, const int* in_sizes, int n_in,
                              void* d_out, int out_size) {
    const float* x      = (const float*)d_in[0];
    const float* memory = (const float*)d_in[1];
    const int*   mask   = (const int*)d_in[2];
    const float* W1     = (const float*)d_in[3];
    const float* b1     = (const float*)d_in[4];
    const float* W2     = (const float*)d_in[5];
    const float* Wt     = (const float*)d_in[6];
    float* out = (float*)d_out;

    // 1) mask compaction (4 tiny CTAs)
    prep_kernel<<<BB, 512>>>(mask);

    // 2) fused projections + output prefill
    const int gsmem = 2 * GK2 * GLD * (int)sizeof(__half2);   // 69632 B
    cudaFuncSetAttribute(gemm_h,
                         cudaFuncAttributeMaxDynamicSharedMemorySize, gsmem);
    dim3 ggrid(2048 / 64, DD / 64, 2);
    gemm_h<<<ggrid, 256, gsmem>>>(x, memory, W1, W2, b1,
                                  (float4*)out, out_size / 4);

    // 3) attention over active columns (8-d unrolled hybrid)
    const int asmem = (DD * S1LD + DD * S2LD + DD) * 4;
    cudaFuncSetAttribute(attn_kernel,
                         cudaFuncAttributeMaxDynamicSharedMemorySize, asmem);
    dim3 agrid(LXN / TXK, LMN / TMK, BB);
    attn_kernel<<<agrid, 256, asmem>>>(Wt, out);
}

// round 14
// speedup vs baseline: 1.0548x; 1.0538x over previous
#include <cuda_runtime.h>
#include <cuda_fp16.h>

#define DD   256
#define BB   4
#define LXN  512
#define LMN  512

#define TXK  32
#define TMK  64
#define S1LD 34      // fp32 leading dim; rows 8B-aligned -> float2 access
#define S2LD 68      // fp32 leading dim; rows 16B-aligned -> float4 access

#define GK2  128     // half2 k-index count (K=256)
#define GLD  68      // gemm smem leading dim (rows + pad), half2 units

__device__ float g_item1t[BB * DD * LXN];   // [b][d][x] fp32
__device__ float g_item2c[BB * DD * LMN];   // [b][d][compacted m] fp32
__device__ int   g_midx[BB * LMN];          // compacted -> original m
__device__ int   g_pos [BB * LMN];          // original m -> compacted (-1)
__device__ int   g_cnt [BB];

__device__ __forceinline__ float fast_tanh(float x) {
    float y;
    asm("tanh.approx.f32 %0, %1;" : "=f"(y) : "f"(x));
    return y;
}

// clamp +-2.5 poly: x*(a + b*x^2 + c*x^4); max abs err ~0.08, exact at clamp
__device__ __forceinline__ float ptanh(float x) {
    float xc = fminf(fmaxf(x, -2.5f), 2.5f);
    float t  = xc * xc;
    return xc * fmaf(t, fmaf(t, 0.018033f, -0.20549f), 0.97444f);
}

extern __shared__ __align__(16) char dynsm[];

// ---------------------------------------------------------------------------
// prep: stable mask compaction only (4 tiny CTAs)
// ---------------------------------------------------------------------------
__global__ __launch_bounds__(512) void prep_kernel(const int* __restrict__ mask) {
    const int b = blockIdx.x;
    const int t = threadIdx.x;
    const int lane = t & 31, w = t >> 5;

    int flag = mask[b * LMN + t] != 0;
    unsigned bal = __ballot_sync(0xffffffffu, flag);
    int pre = __popc(bal & ((1u << lane) - 1u));

    __shared__ int wcnt[16], woff[16], s_n;
    if (lane == 0) wcnt[w] = __popc(bal);
    __syncthreads();
    if (t == 0) {
        int s = 0;
        for (int i = 0; i < 16; ++i) { woff[i] = s; s += wcnt[i]; }
        s_n = s;
        g_cnt[b] = s;
    }
    __syncthreads();
    int p = woff[w] + pre;
    g_pos[b * LMN + t] = flag ? p : -1;
    if (flag) g_midx[b * LMN + p] = t;
    __syncthreads();

    const int n = s_n;   // pad indices for the tail tile's int4 reads
    if (n > 0) {
        const int padded = (n + TMK - 1) / TMK * TMK;
        if (t >= n && t < padded)
            g_midx[b * LMN + t] = g_midx[b * LMN + n - 1];
    }
}

// ---------------------------------------------------------------------------
// Fused NT-GEMM pair (single-load smem, HFMA2 core, fp32 out) + output
// prefill with -10000 at the kernel head.
// ---------------------------------------------------------------------------
__global__ __launch_bounds__(256) void gemm_h(const float* __restrict__ Xin,
                                              const float* __restrict__ Min,
                                              const float* __restrict__ W1,
                                              const float* __restrict__ W2,
                                              const float* __restrict__ b1,
                                              float4* __restrict__ out4,
                                              int n4) {
    __half2* As2 = (__half2*)dynsm;             // [GK2][GLD]
    __half2* Ws2 = As2 + GK2 * GLD;             // [GK2][GLD]

    const int tid = threadIdx.x;

    // --- output prefill slice (256 CTAs x 256 thr cover n4 = 1M float4)
    {
        const int bid = blockIdx.x + 32 * (blockIdx.y + 4 * blockIdx.z);
        const float4 v = make_float4(-10000.f, -10000.f, -10000.f, -10000.f);
        for (int i = bid * 256 + tid; i < n4; i += 256 * 256)
            out4[i] = v;
    }

    const int which = blockIdx.z;
    const float* A = which ? Min : Xin;
    const float* W = which ? W2  : W1;

    const int m0 = blockIdx.x * 64;
    const int n0 = blockIdx.y * 64;
    const int tx = tid & 15;
    const int ty = tid >> 4;
    const int lr = tid >> 2;        // load row 0..63
    const int lj = tid & 3;         // float4 column group

    #pragma unroll
    for (int i = 0; i < 16; ++i) {
        const int j4 = lj + (i << 2);                 // float4 idx 0..63
        float4 av = *(const float4*)&A[(m0 + lr) * DD + j4 * 4];
        float4 wv = *(const float4*)&W[(n0 + lr) * DD + j4 * 4];
        const int k2 = 2 * j4;
        As2[(k2 + 0) * GLD + lr] = __floats2half2_rn(av.x, av.y);
        As2[(k2 + 1) * GLD + lr] = __floats2half2_rn(av.z, av.w);
        Ws2[(k2 + 0) * GLD + lr] = __floats2half2_rn(wv.x, wv.y);
        Ws2[(k2 + 1) * GLD + lr] = __floats2half2_rn(wv.z, wv.w);
    }
    __syncthreads();

    float accf[4][4] = {};
    const __half2 hz = __float2half2_rn(0.f);

    #pragma unroll 1
    for (int kc = 0; kc < GK2; kc += 32) {     // flush fp32 every 64 k
        __half2 acc2[4][4];
        #pragma unroll
        for (int i = 0; i < 4; ++i)
            #pragma unroll
            for (int j = 0; j < 4; ++j) acc2[i][j] = hz;

        #pragma unroll 8
        for (int k2 = kc; k2 < kc + 32; ++k2) {
            uint4 au = *(const uint4*)&As2[k2 * GLD + tx * 4];
            uint4 wu = *(const uint4*)&Ws2[k2 * GLD + ty * 4];
            __half2 ar[4], wr[4];
            ar[0] = *reinterpret_cast<__half2*>(&au.x);
            ar[1] = *reinterpret_cast<__half2*>(&au.y);
            ar[2] = *reinterpret_cast<__half2*>(&au.z);
            ar[3] = *reinterpret_cast<__half2*>(&au.w);
            wr[0] = *reinterpret_cast<__half2*>(&wu.x);
            wr[1] = *reinterpret_cast<__half2*>(&wu.y);
            wr[2] = *reinterpret_cast<__half2*>(&wu.z);
            wr[3] = *reinterpret_cast<__half2*>(&wu.w);
            #pragma unroll
            for (int i = 0; i < 4; ++i)
                #pragma unroll
                for (int j = 0; j < 4; ++j)
                    acc2[i][j] = __hfma2(ar[i], wr[j], acc2[i][j]);
        }
        #pragma unroll
        for (int i = 0; i < 4; ++i)
            #pragma unroll
            for (int j = 0; j < 4; ++j) {
                float2 t = __half22float2(acc2[i][j]);
                accf[i][j] += t.x + t.y;
            }
    }

    const int r_base = m0 + tx * 4;
    const int bb = r_base >> 9;
    const int lb = r_base & 511;

    if (!which) {
        float4 bv = *(const float4*)&b1[n0 + ty * 4];
        float bj[4] = {bv.x, bv.y, bv.z, bv.w};
        #pragma unroll
        for (int j = 0; j < 4; ++j) {
            int d = n0 + ty * 4 + j;
            float4 v;
            v.x = accf[0][j] + bj[j];
            v.y = accf[1][j] + bj[j];
            v.z = accf[2][j] + bj[j];
            v.w = accf[3][j] + bj[j];
            *(float4*)&g_item1t[((bb * DD + d) * LXN) + lb] = v;
        }
    } else {
        int4 pi = *(const int4*)&g_pos[bb * LMN + lb];
        int pos[4] = {pi.x, pi.y, pi.z, pi.w};
        #pragma unroll
        for (int j = 0; j < 4; ++j) {
            int d = n0 + ty * 4 + j;
            float* dst = g_item2c + (bb * DD + d) * LMN;
            #pragma unroll
            for (int i = 0; i < 4; ++i)
                if (pos[i] >= 0)
                    dst[pos[i]] = accf[i][j];
        }
    }
}

// ---------------------------------------------------------------------------
// attn over ACTIVE m-columns, fp32. NEW hybrid: per d, the m-column (d&3)
// uses the FMA-pipe polynomial while the other 3 columns use MUFU tanh —
// 6 MUFU + 2 poly elems per thread per d, so BOTH pipes are busy in the
// SAME cycles (no phase alternation). Per-element poly fraction stays 1/4.
// ---------------------------------------------------------------------------
__global__ __launch_bounds__(256) void attn_kernel(const float* __restrict__ Wt,
                                                   float* __restrict__ out) {
    const int b  = blockIdx.z;
    const int m0 = blockIdx.y * TMK;
    const int n_act = g_cnt[b];
    if (m0 >= n_act) return;

    float* s1  = (float*)dynsm;          // [DD][S1LD]
    float* s2  = s1 + DD * S1LD;         // [DD][S2LD]
    float* swt = s2 + DD * S2LD;         // [DD]

    const int tid = threadIdx.x;
    const int x0 = blockIdx.x * TXK;

    {
        const int d = tid;
        const float2* p1 = (const float2*)(g_item1t + (b * DD + d) * LXN + x0);
        float2* q1 = (float2*)(s1 + d * S1LD);
        #pragma unroll
        for (int j = 0; j < 16; ++j) q1[j] = p1[j];

        const float4* p2 = (const float4*)(g_item2c + (b * DD + d) * LMN + m0);
        float* q2 = s2 + d * S2LD;
        #pragma unroll
        for (int j = 0; j < 16; ++j) *(float4*)(q2 + j * 4) = p2[j];

        swt[d] = Wt[d];
    }
    __syncthreads();

    const int tx = tid & 15;
    const int tm = tid >> 4;
    const float* s1p = s1 + tx * 2;
    const float* s2p = s2 + tm * 4;

    float acc[2][4] = {};

    #pragma unroll 1
    for (int d0 = 0; d0 < DD; d0 += 4) {
        #pragma unroll
        for (int dd = 0; dd < 4; ++dd) {      // dd == poly column this d
            const int d = d0 + dd;
            const float w  = swt[d];
            const float2 a = *(const float2*)(s1p + d * S1LD);
            const float4 m4 = *(const float4*)(s2p + d * S2LD);
            const float mm[4] = {m4.x, m4.y, m4.z, m4.w};
            #pragma unroll
            for (int j = 0; j < 4; ++j) {
                const float v0 = a.x + mm[j];
                const float v1 = a.y + mm[j];
                float t0, t1;
                if (j == dd) { t0 = ptanh(v0);     t1 = ptanh(v1); }
                else         { t0 = fast_tanh(v0); t1 = fast_tanh(v1); }
                acc[0][j] += t0 * w;
                acc[1][j] += t1 * w;
            }
        }
    }

    // predicated scatter-store: only truly active columns write
    const int c0 = m0 + tm * 4;
    int4 mi = *(const int4*)&g_midx[b * LMN + c0];
    bool v0 = (c0 + 0) < n_act, v1 = (c0 + 1) < n_act;
    bool v2 = (c0 + 2) < n_act, v3 = (c0 + 3) < n_act;
    const int x = x0 + tx * 2;
    float* r0 = out + (b * LXN + x) * (long)LMN;
    float* r1 = r0 + LMN;
    if (v0) { r0[mi.x] = acc[0][0]; r1[mi.x] = acc[1][0]; }
    if (v1) { r0[mi.y] = acc[0][1]; r1[mi.y] = acc[1][1]; }
    if (v2) { r0[mi.z] = acc[0][2]; r1[mi.z] = acc[1][2]; }
    if (v3) { r0[mi.w] = acc[0][3]; r1[mi.w] = acc[1][3]; }
}

// ---------------------------------------------------------------------------

extern "C" void kernel_launch(void* const* d_in, const int* in_sizes, int n_in,
                              void* d_out, int out_size) {
    const float* x      = (const float*)d_in[0];
    const float* memory = (const float*)d_in[1];
    const int*   mask   = (const int*)d_in[2];
    const float* W1     = (const float*)d_in[3];
    const float* b1     = (const float*)d_in[4];
    const float* W2     = (const float*)d_in[5];
    const float* Wt     = (const float*)d_in[6];
    float* out = (float*)d_out;

    // 1) mask compaction (4 tiny CTAs)
    prep_kernel<<<BB, 512>>>(mask);

    // 2) fused projections + output prefill
    const int gsmem = 2 * GK2 * GLD * (int)sizeof(__half2);   // 69632 B
    cudaFuncSetAttribute(gemm_h,
                         cudaFuncAttributeMaxDynamicSharedMemorySize, gsmem);
    dim3 ggrid(2048 / 64, DD / 64, 2);
    gemm_h<<<ggrid, 256, gsmem>>>(x, memory, W1, W2, b1,
                                  (float4*)out, out_size / 4);

    // 3) attention over active columns (per-d interleaved MUFU/poly hybrid)
    const int asmem = (DD * S1LD + DD * S2LD + DD) * 4;
    cudaFuncSetAttribute(attn_kernel,
                         cudaFuncAttributeMaxDynamicSharedMemorySize, asmem);
    dim3 agrid(LXN / TXK, LMN / TMK, BB);
    attn_kernel<<<agrid, 256, asmem>>>(Wt, out);
}